// round 17
// baseline (speedup 1.0000x reference)
#include <cuda_runtime.h>
#include <math.h>

#define Bsz 8
#define Lseq 2048
#define INF 64
#define OUTF 64
#define Hd 128
#define Nst 64
#define NLAY 4
#define L2 4096
#define ROWS (Bsz*Lseq)

typedef unsigned long long ull;

// ---------------- persistent scratch ----------------
__device__ float  g_h  [ROWS*Hd];
__device__ float  g_hnT[Bsz*Hd*Lseq];
__device__ float  g_yT [Bsz*Hd*Lseq];
__device__ float4 g_KdP[NLAY*(Hd/2)*Lseq];
__device__ float2 g_KdN[NLAY*Hd];
__device__ float2 g_tw [L2/2];
__device__ float  g_w1T[NLAY*Hd*Hd];
__device__ float  g_w2T[NLAY*Hd*Hd];
__device__ float  g_encWT[INF*Hd];
__device__ float  g_decWT[Hd*OUTF];

__device__ __forceinline__ float2 cmulf(float2 a, float2 b) {
    return make_float2(a.x*b.x - a.y*b.y, a.x*b.y + a.y*b.x);
}
__device__ __forceinline__ float2 caddf(float2 a, float2 b){ return make_float2(a.x+b.x, a.y+b.y); }
__device__ __forceinline__ float2 csubf(float2 a, float2 b){ return make_float2(a.x-b.x, a.y-b.y); }
__device__ __forceinline__ float2 addi(float2 a, float2 d, float sgn) {
    return make_float2(a.x - sgn*d.y, a.y + sgn*d.x);
}
__device__ __forceinline__ ull pk(float x, float y) {
    ull r; asm("mov.b64 %0, {%1, %2};" : "=l"(r) : "f"(x), "f"(y)); return r;
}
__device__ __forceinline__ void upk(ull p, float& x, float& y) {
    asm("mov.b64 {%0, %1}, %2;" : "=f"(x), "=f"(y) : "l"(p));
}
__device__ __forceinline__ ull ffma2(ull a, ull b, ull c) {
    ull d; asm("fma.rn.f32x2 %0, %1, %2, %3;" : "=l"(d) : "l"(a), "l"(b), "l"(c)); return d;
}
__device__ __forceinline__ void cpa16(unsigned dst, const void* src) {
    asm volatile("cp.async.cg.shared.global [%0], [%1], 16;" :: "r"(dst), "l"(src));
}
#define CP_COMMIT() asm volatile("cp.async.commit_group;" ::: "memory")
#define CP_WAIT(n)  asm volatile("cp.async.wait_group %0;" :: "n"(n) : "memory")

// ---------------- prep: twiddles + weight transposes ----------------
__global__ void prep_kernel(const float* __restrict__ enc_w, const float* __restrict__ dec_w,
                            const float* __restrict__ w1, const float* __restrict__ w2) {
    int tid = blockIdx.x * 256 + threadIdx.x;
    if (tid < L2/2) {
        float s, c;
        sincospif(-(float)tid / 2048.0f, &s, &c);
        g_tw[tid] = make_float2(c, s);
    }
    if (tid < INF*Hd) { int k = tid >> 7, c = tid & 127; g_encWT[tid] = enc_w[c*INF + k]; }
    if (tid < Hd*OUTF) { int k = tid >> 6, o = tid & 63; g_decWT[tid] = dec_w[o*Hd + k]; }
    if (tid < NLAY*Hd*Hd) {
        int lay = tid >> 14, r = tid & 16383, k = r >> 7, c = r & 127;
        g_w1T[tid] = w1[lay*Hd*Hd + c*Hd + k];
        g_w2T[tid] = w2[lay*Hd*Hd + c*Hd + k];
    }
}

// ---------------- radix-8 butterfly ----------------
__device__ __forceinline__ void radix8(const float2 u[8],
                                       float2 w1, float2 w2, float2 w3, float2 w4,
                                       float sgnF, float2 out[8]) {
    const float cc = 0.70710678118654752f;
    float2 w5 = cmulf(w4, w1);
    float2 w6 = cmulf(w3, w3);
    float2 w7 = cmulf(w4, w3);
    float2 t0 = u[0];
    float2 t1 = cmulf(w1, u[1]);
    float2 t2 = cmulf(w2, u[2]);
    float2 t3 = cmulf(w3, u[3]);
    float2 t4 = cmulf(w4, u[4]);
    float2 t5 = cmulf(w5, u[5]);
    float2 t6 = cmulf(w6, u[6]);
    float2 t7 = cmulf(w7, u[7]);
    float2 s04 = caddf(t0, t4), d04 = csubf(t0, t4);
    float2 s26 = caddf(t2, t6), d26 = csubf(t2, t6);
    float2 s15 = caddf(t1, t5), d15 = csubf(t1, t5);
    float2 s37 = caddf(t3, t7), d37 = csubf(t3, t7);
    float2 E0 = caddf(s04, s26), E2 = csubf(s04, s26);
    float2 E1 = addi(d04, d26, sgnF), E3 = addi(d04, d26, -sgnF);
    float2 O0 = caddf(s15, s37), O2 = csubf(s15, s37);
    float2 O1 = addi(d15, d37, sgnF), O3 = addi(d15, d37, -sgnF);
    float2 W81 = make_float2(cc,  sgnF*cc);
    float2 W83 = make_float2(-cc, sgnF*cc);
    float2 p1 = cmulf(O1, W81);
    float2 p2 = make_float2(-sgnF*O2.y, sgnF*O2.x);
    float2 p3 = cmulf(O3, W83);
    out[0] = caddf(E0, O0); out[4] = csubf(E0, O0);
    out[1] = caddf(E1, p1); out[5] = csubf(E1, p1);
    out[2] = caddf(E2, p2); out[6] = csubf(E2, p2);
    out[3] = caddf(E3, p3); out[7] = csubf(E3, p3);
}

// ---------------- 2048-pt Stockham FFT (double-buffered; ckfft only) ----------------
__device__ float2* fft2048_m(float2* a, float2* b, bool inverse) {
    float2* src = a; float2* dst = b;
    const float sgnF = inverse ? 1.0f : -1.0f;
    __syncthreads();
    for (int j = threadIdx.x; j < 512; j += blockDim.x) {
        float2 u0 = src[j], u1 = src[j+512], u2 = src[j+1024], u3 = src[j+1536];
        float2 a02 = caddf(u0, u2), s02 = csubf(u0, u2);
        float2 a13 = caddf(u1, u3), s13 = csubf(u1, u3);
        int o = j << 2;
        dst[o  ] = caddf(a02, a13);
        dst[o+1] = addi(s02, s13, sgnF);
        dst[o+2] = csubf(a02, a13);
        dst[o+3] = addi(s02, s13, -sgnF);
    }
    { float2* tmp = src; src = dst; dst = tmp; }
    int L = 4, mult = 128;
    #pragma unroll
    for (int t = 0; t < 3; t++) {
        __syncthreads();
        for (int j = threadIdx.x; j < 256; j += blockDim.x) {
            int k = j & (L - 1);
            int blk = j >> (2 + 3*t);
            float2 u[8];
            #pragma unroll
            for (int i = 0; i < 8; i++) u[i] = src[j + i*256];
            int idx = k * mult;
            float2 w1 = g_tw[idx], w2 = g_tw[2*idx], w3 = g_tw[3*idx], w4 = g_tw[4*idx];
            if (inverse) { w1.y = -w1.y; w2.y = -w2.y; w3.y = -w3.y; w4.y = -w4.y; }
            float2 o8[8];
            radix8(u, w1, w2, w3, w4, sgnF, o8);
            int o = (blk << 3)*L + k;
            #pragma unroll
            for (int i = 0; i < 8; i++) dst[o + i*L] = o8[i];
        }
        { float2* tmp = src; src = dst; dst = tmp; }
        L <<= 3; mult >>= 3;
    }
    __syncthreads();
    return src;
}

// ---------------- one in-place radix-8 stage (4096 pts, 256 threads) ----------------
__device__ __forceinline__ void stage_ip(float2* A, int t, int L, int mult,
                                         float sgnF, bool conj) {
    float2 u[2][8];
    #pragma unroll
    for (int q = 0; q < 2; q++) {
        int j = threadIdx.x + q*256;
        #pragma unroll
        for (int i = 0; i < 8; i++) u[q][i] = A[j + i*512];
    }
    __syncthreads();
    #pragma unroll
    for (int q = 0; q < 2; q++) {
        int j = threadIdx.x + q*256;
        int k = j & (L - 1);
        int blkq = j >> (3*t);
        int idx = k * mult;
        float2 w1 = g_tw[idx], w2 = g_tw[2*idx], w3 = g_tw[3*idx], w4 = g_tw[4*idx];
        if (conj) { w1.y = -w1.y; w2.y = -w2.y; w3.y = -w3.y; w4.y = -w4.y; }
        float2 o8[8];
        radix8(u[q], w1, w2, w3, w4, sgnF, o8);
        int o = (blkq << (3*t + 3)) + k;
        #pragma unroll
        for (int i = 0; i < 8; i++) A[o + i*L] = o8[i];
    }
    __syncthreads();
}

// ---------------- FFT causal conv (R14 winner, unchanged) ----------------
__global__ __launch_bounds__(256, 4) void conv_kernel(const float* __restrict__ dvec, int lay) {
    __shared__ float2 A[L2];
    int blk = blockIdx.x;
    int b = blk >> 6, hp = blk & 63;
    int h0 = 2*hp;
    int tid = threadIdx.x;
    const float* u1 = g_hnT + ((size_t)b*Hd + h0)*Lseq;
    const float* u2 = u1 + Lseq;
    const float2 ONE = make_float2(1.f, 0.f);

    #pragma unroll
    for (int q = 0; q < 2; q++) {
        int j = tid + q*256;
        float2 u[8], o8[8];
        #pragma unroll
        for (int i = 0; i < 4; i++) u[i] = make_float2(u1[j + i*512], u2[j + i*512]);
        #pragma unroll
        for (int i = 4; i < 8; i++) u[i] = make_float2(0.f, 0.f);
        radix8(u, ONE, ONE, ONE, ONE, -1.0f, o8);
        #pragma unroll
        for (int i = 0; i < 8; i++) A[(j << 3) + i] = o8[i];
    }
    __syncthreads();
    stage_ip(A, 1, 8,   64, -1.0f, false);
    stage_ip(A, 2, 64,  8,  -1.0f, false);
    stage_ip(A, 3, 512, 1,  -1.0f, false);

    const float4* KP = g_KdP + ((size_t)lay*(Hd/2) + hp)*Lseq;
    #pragma unroll
    for (int s = 0; s < 8; s++) {
        int f  = tid + s*256;
        int fr = (L2 - f) & (L2-1);
        float2 zf = A[f], zr = A[fr];
        float4 K = KP[f];
        float2 K1 = make_float2(K.x, K.y), K2 = make_float2(K.z, K.w);
        float2 U1 = make_float2(0.5f*(zf.x + zr.x),  0.5f*(zf.y - zr.y));
        float2 U2 = make_float2(0.5f*(zf.y + zr.y), -0.5f*(zf.x - zr.x));
        float2 Y1 = cmulf(U1, K1);
        float2 Y2 = cmulf(U2, K2);
        A[f] = make_float2(Y1.x - Y2.y, Y1.y + Y2.x);
        if (f != 0)
            A[fr] = make_float2(Y1.x + Y2.y, Y2.x - Y1.y);
        if (f == 0) {
            float2 z = A[2048];
            float2 K1n = g_KdN[lay*Hd + h0];
            float2 K2n = g_KdN[lay*Hd + h0 + 1];
            float2 Y1n = make_float2(z.x*K1n.x, z.x*K1n.y);
            float2 Y2n = make_float2(z.y*K2n.x, z.y*K2n.y);
            A[2048] = make_float2(Y1n.x - Y2n.y, Y1n.y + Y2n.x);
        }
    }
    __syncthreads();

    {
        float2 u[2][8];
        #pragma unroll
        for (int q = 0; q < 2; q++) {
            int j = tid + q*256;
            #pragma unroll
            for (int i = 0; i < 8; i++) u[q][i] = A[j + i*512];
        }
        __syncthreads();
        #pragma unroll
        for (int q = 0; q < 2; q++) {
            int j = tid + q*256;
            float2 o8[8];
            radix8(u[q], ONE, ONE, ONE, ONE, 1.0f, o8);
            #pragma unroll
            for (int i = 0; i < 8; i++) A[(j << 3) + i] = o8[i];
        }
        __syncthreads();
    }
    stage_ip(A, 1, 8,  64, 1.0f, true);
    stage_ip(A, 2, 64, 8,  1.0f, true);
    {
        float d1 = dvec[h0], d2 = dvec[h0+1];
        float* y1 = g_yT + ((size_t)b*Hd + h0)*Lseq;
        float* y2 = y1 + Lseq;
        float2 u[2][8];
        #pragma unroll
        for (int q = 0; q < 2; q++) {
            int j = tid + q*256;
            #pragma unroll
            for (int i = 0; i < 8; i++) u[q][i] = A[j + i*512];
        }
        #pragma unroll
        for (int q = 0; q < 2; q++) {
            int j = tid + q*256;
            int idx = j;
            float2 w1 = g_tw[idx], w2 = g_tw[2*idx], w3 = g_tw[3*idx], w4 = g_tw[4*idx];
            w1.y = -w1.y; w2.y = -w2.y; w3.y = -w3.y; w4.y = -w4.y;
            float2 o8[8];
            radix8(u[q], w1, w2, w3, w4, 1.0f, o8);
            #pragma unroll
            for (int i = 0; i < 4; i++) {
                int l = j + i*512;
                float v1 = o8[i].x*(1.0f/L2) + u1[l]*d1;
                float v2 = o8[i].y*(1.0f/L2) + u2[l]*d2;
                float t1 = 0.7978845608028654f * (v1 + 0.044715f * v1*v1*v1);
                float t2 = 0.7978845608028654f * (v2 + 0.044715f * v2*v2*v2);
                y1[l] = 0.5f * v1 * (1.0f + tanhf(t1));
                y2[l] = 0.5f * v2 * (1.0f + tanhf(t2));
            }
        }
    }
}

// ---------------- FRONT: ckfft blocks (0..511) || encoder blocks (512..1023) ----------------
__global__ __launch_bounds__(512) void front_kernel(
        const float* __restrict__ x, const float* __restrict__ eb,
        const float* __restrict__ nw, const float* __restrict__ nb,
        const float* __restrict__ lre, const float* __restrict__ lim,
        const float* __restrict__ pre, const float* __restrict__ pim,
        const float* __restrict__ bre, const float* __restrict__ bim,
        const float* __restrict__ cre, const float* __restrict__ cim,
        const float* __restrict__ lstep) {
    extern __shared__ __align__(16) char dynbuf[];
    int blk = blockIdx.x;
    int tid = threadIdx.x;
    if (blk < 512) {
        float2* A  = (float2*)dynbuf;
        float2* Bb = A + Lseq;
        __shared__ float2 slam[Nst];
        __shared__ ull sp[4][Nst][2];
        int lay = blk >> 7, h = blk & 127;
        int hh = lay*Hd + h;
        if (tid < Nst) {
            int idx = hh*Nst + tid;
            slam[tid] = make_float2(lre[idx], lim[idx]);
            float2 P  = make_float2(pre[idx], pim[idx]);
            float2 Bv = make_float2(bre[idx], bim[idx]);
            float2 Cc = make_float2(cre[idx], -cim[idx]);
            float2 Pc = make_float2(P.x, -P.y);
            float2 vm[4];
            vm[0] = cmulf(Cc, Bv); vm[1] = cmulf(Cc, P);
            vm[2] = cmulf(Pc, Bv); vm[3] = cmulf(Pc, P);
            #pragma unroll
            for (int m = 0; m < 4; m++) {
                sp[m][tid][0] = pk(vm[m].x, vm[m].y);
                sp[m][tid][1] = pk(vm[m].y, -vm[m].x);
            }
        }
        __syncthreads();
        float ts = 2.0f / __expf(lstep[hh]);
        for (int l = tid; l < Lseq; l += 512) {
            // XLA-style omega (f32 angle + sincosf; l=L/2 must NOT be exactly -1)
            float ang = -6.2831853071795864f * ((float)l / (float)Lseq);
            float s, c;
            sincosf(ang, &s, &c);
            float dpx = 1.0f + c, dpy = s;
            float dmx = 1.0f - c, dmy = -s;
            float id2 = __fdividef(1.0f, dpx*dpx + dpy*dpy);
            float gx = ts * (dmx*dpx + dmy*dpy) * id2;
            float gy = ts * (dmy*dpx - dmx*dpy) * id2;
            float c2x = 2.0f*dpx*id2, c2y = -2.0f*dpy*id2;
            ull acc[4] = {0ull, 0ull, 0ull, 0ull};
            #pragma unroll 8
            for (int n = 0; n < Nst; n++) {
                float dx = gx - slam[n].x;
                float dy = gy - slam[n].y;
                float inv = __fdividef(1.0f, dx*dx + dy*dy);
                float rx = dx*inv, ryp = dy*inv;
                ull rxx = pk(rx, rx), ryy = pk(ryp, ryp);
                #pragma unroll
                for (int m = 0; m < 4; m++)
                    acc[m] = ffma2(sp[m][n][0], rxx, ffma2(sp[m][n][1], ryy, acc[m]));
            }
            float k00x,k00y,k01x,k01y,k10x,k10y,k11x,k11y;
            upk(acc[0], k00x, k00y); upk(acc[1], k01x, k01y);
            upk(acc[2], k10x, k10y); upk(acc[3], k11x, k11y);
            float opx = 1.0f + k11x, opy = k11y;
            float oinv = __fdividef(1.0f, opx*opx + opy*opy);
            float wx = k01x*k10x - k01y*k10y;
            float wy = k01x*k10y + k01y*k10x;
            float cx = (wx*opx + wy*opy) * oinv;
            float cy = (wy*opx - wx*opy) * oinv;
            float rx2 = k00x - cx, ry2 = k00y - cy;
            A[l] = make_float2(c2x*rx2 - c2y*ry2, c2x*ry2 + c2y*rx2);
        }
        __syncthreads();
        float2* KP2 = (float2*)(g_KdP + ((size_t)lay*(Hd/2) + (h>>1))*Lseq);
        int slot = h & 1;
        for (int m = tid; m < Lseq; m += 512) {
            if (m < 1024) {
                float2 am = A[m];
                float2 ar = A[(Lseq - m) & (Lseq-1)];
                KP2[4*m + slot] = make_float2(0.5f*(am.x + ar.x), 0.5f*(am.y - ar.y));
            } else if (m == 1024) {
                g_KdN[hh] = make_float2(A[1024].x, 0.f);
            }
        }
        float2* r = fft2048_m(A, Bb, true);
        for (int m = tid; m < Lseq; m += 512) {
            float xr = r[m].x * (1.0f/Lseq);
            float2 w = g_tw[m];
            Bb[m] = make_float2(xr * w.x, xr * w.y);
        }
        float2* r2 = fft2048_m(Bb, A, false);
        for (int m = tid; m < 1024; m += 512)
            KP2[4*m + 2 + slot] = r2[m];
    } else {
        float* xs   = (float*)dynbuf;
        ull*   zs2b = (ull*)(dynbuf + 8192);
        float* tile = (float*)(dynbuf + 8192 + 8704);
        int row0 = (blk - 512) * 32;
        int b = row0 >> 11, l0 = row0 & 2047;
        for (int idx = tid; idx < 32*INF; idx += 512)
            xs[idx] = x[(size_t)(row0 + (idx >> 6))*INF + (idx & 63)];
        __syncthreads();
        for (int idx = tid; idx < INF*16; idx += 512) {
            int p = idx >> 6, k = idx & 63;
            zs2b[k*17 + p] = pk(xs[(2*p)*INF + k], xs[(2*p+1)*INF + k]);
        }
        __syncthreads();
        int c = tid & 127, quar = tid >> 7;
        int p0 = quar * 4;
        ull acc[4];
        {
            float bv = eb[c];
            ull bp = pk(bv, bv);
            #pragma unroll
            for (int p = 0; p < 4; p++) acc[p] = bp;
        }
        #pragma unroll 4
        for (int k = 0; k < INF; k++) {
            float wv = g_encWT[k*Hd + c];
            ull wp = pk(wv, wv);
            #pragma unroll
            for (int p = 0; p < 4; p++) acc[p] = ffma2(zs2b[k*17 + p0 + p], wp, acc[p]);
        }
        #pragma unroll
        for (int p = 0; p < 4; p++) {
            float h0v, h1v;
            upk(acc[p], h0v, h1v);
            int ra = 2*(p0 + p), rb = ra + 1;
            g_h[(size_t)(row0 + ra)*Hd + c] = h0v;
            g_h[(size_t)(row0 + rb)*Hd + c] = h1v;
            tile[ra*129 + c] = h0v; tile[rb*129 + c] = h1v;
        }
        __syncthreads();
        int warp = tid >> 5, lane = tid & 31;
        #pragma unroll
        for (int rr = 0; rr < 2; rr++) {
            int l = warp*2 + rr;
            float v[4]; float sum = 0.f;
            #pragma unroll
            for (int i = 0; i < 4; i++) { v[i] = tile[l*129 + lane + 32*i]; sum += v[i]; }
            #pragma unroll
            for (int o = 16; o; o >>= 1) sum += __shfl_xor_sync(0xffffffffu, sum, o);
            float mu = sum * (1.0f/Hd);
            float var = 0.f;
            #pragma unroll
            for (int i = 0; i < 4; i++) { float t = v[i]-mu; var += t*t; }
            #pragma unroll
            for (int o = 16; o; o >>= 1) var += __shfl_xor_sync(0xffffffffu, var, o);
            float rstd = rsqrtf(var * (1.0f/Hd) + 1e-5f);
            #pragma unroll
            for (int i = 0; i < 4; i++) {
                int cc = lane + 32*i;
                tile[l*129 + cc] = (v[i]-mu)*rstd*nw[cc] + nb[cc];
            }
        }
        __syncthreads();
        for (int idx = tid; idx < 32*Hd; idx += 512) {
            int hh = idx >> 5, l = idx & 31;
            g_hnT[((size_t)(b*Hd + hh))*Lseq + l0 + l] = tile[l*129 + hh];
        }
    }
}

// ---------------- gated MLP: cp.async-staged weights + residual + LN / decoder ----------------
#define MLP_SMBUF 33152                       // zs2 [128][32] ull (32768) / tile [64][129] f32 (33024), padded
#define MLP_WOFF  MLP_SMBUF                   // weight ring: 2 bufs x 8192 floats
#define MLP_SMEM  (MLP_SMBUF + 2*8192*4)      // 98688 B

__global__ __launch_bounds__(512, 2) void mlp_kernel(const float* __restrict__ b1,
                                                     const float* __restrict__ b2,
                                                     const float* __restrict__ nw,
                                                     const float* __restrict__ nb,
                                                     const float* __restrict__ dec_bias,
                                                     float* __restrict__ out,
                                                     int lay, int do_ln) {
    const float* __restrict__ w1T = g_w1T + lay*Hd*Hd;
    const float* __restrict__ w2T = g_w2T + lay*Hd*Hd;
    extern __shared__ __align__(16) unsigned char dsm[];
    ull   (*zs2)[32]   = reinterpret_cast<ull(*)[32]>(dsm);
    float (*tile)[129] = reinterpret_cast<float(*)[129]>(dsm);
    float* wbuf = (float*)(dsm + MLP_WOFF);
    unsigned wbase = (unsigned)__cvta_generic_to_shared(wbuf);
    int row0 = blockIdx.x * 64;
    int b = row0 >> 11, l0 = row0 & 2047;
    int tid = threadIdx.x;
    int c = tid & 127, grp = tid >> 7;

    // prefetch weight chunk 0 into buf 0 (2048 float4 per chunk: w1 first 1024, w2 next)
    {
        const float4* w1c = (const float4*)w1T;
        const float4* w2c = (const float4*)w2T;
        #pragma unroll
        for (int j = 0; j < 2; j++) {
            int i = tid + j*512;
            cpa16(wbase + (unsigned)i*16, w1c + i);
            cpa16(wbase + 16384u + (unsigned)i*16, w2c + i);
        }
        CP_COMMIT();
    }

    for (int idx = tid; idx < Hd*32; idx += 512) {
        int k = idx >> 5, p = idx & 31;
        float2 v = *(const float2*)&g_yT[((size_t)(b*Hd + k))*Lseq + l0 + 2*p];
        zs2[k][p] = pk(v.x, v.y);
    }
    int p0 = grp * 8;
    ull acc1[8], acc2[8];
    {
        float b1v = b1[c], b2v = b2[c];
        ull p1 = pk(b1v, b1v), p2 = pk(b2v, b2v);
        #pragma unroll
        for (int p = 0; p < 8; p++) { acc1[p] = p1; acc2[p] = p2; }
    }
    #pragma unroll
    for (int kc = 0; kc < 4; kc++) {
        if (kc < 3) {  // prefetch next chunk into other buffer
            const float4* w1c = (const float4*)(w1T + (kc+1)*4096);
            const float4* w2c = (const float4*)(w2T + (kc+1)*4096);
            unsigned wb = wbase + (unsigned)(((kc+1)&1) * 32768);
            #pragma unroll
            for (int j = 0; j < 2; j++) {
                int i = tid + j*512;
                cpa16(wb + (unsigned)i*16, w1c + i);
                cpa16(wb + 16384u + (unsigned)i*16, w2c + i);
            }
            CP_COMMIT();
            CP_WAIT(1);
        } else {
            CP_WAIT(0);
        }
        __syncthreads();   // chunk kc resident (and zs2 ready on first iter)
        const float* wb1 = wbuf + (kc&1)*8192;
        const float* wb2 = wb1 + 4096;
        #pragma unroll 4
        for (int kk = 0; kk < 32; kk++) {
            int k = kc*32 + kk;
            float w1v = wb1[kk*128 + c];
            float w2v = wb2[kk*128 + c];
            const float4* z4 = reinterpret_cast<const float4*>(&zs2[k][p0]);
            float4 za = z4[0], zb = z4[1], zc = z4[2], zd = z4[3];
            ull w1p = pk(w1v, w1v), w2p = pk(w2v, w2v);
            ull zp[8];
            zp[0] = pk(za.x, za.y); zp[1] = pk(za.z, za.w);
            zp[2] = pk(zb.x, zb.y); zp[3] = pk(zb.z, zb.w);
            zp[4] = pk(zc.x, zc.y); zp[5] = pk(zc.z, zc.w);
            zp[6] = pk(zd.x, zd.y); zp[7] = pk(zd.z, zd.w);
            #pragma unroll
            for (int p = 0; p < 8; p++) {
                acc1[p] = ffma2(zp[p], w1p, acc1[p]);
                acc2[p] = ffma2(zp[p], w2p, acc2[p]);
            }
        }
        __syncthreads();   // protect buf (kc&1) before prefetch kc+2 overwrites it
    }
    #pragma unroll
    for (int p = 0; p < 8; p++) {
        float o0, o1, g0, g1;
        upk(acc1[p], o0, o1);
        upk(acc2[p], g0, g1);
        int ra = 2*(p0 + p), rb = ra + 1;
        size_t ia = (size_t)(row0 + ra)*Hd + c;
        size_t ib = (size_t)(row0 + rb)*Hd + c;
        float ha = g_h[ia] + o0 / (1.0f + __expf(-g0));
        float hb = g_h[ib] + o1 / (1.0f + __expf(-g1));
        if (do_ln) { g_h[ia] = ha; g_h[ib] = hb; }
        tile[ra][c] = ha; tile[rb][c] = hb;
    }
    __syncthreads();
    if (do_ln) {
        int warp = tid >> 5, lane = tid & 31;
        #pragma unroll
        for (int rr = 0; rr < 4; rr++) {
            int l = warp*4 + rr;
            float v[4]; float sum = 0.f;
            #pragma unroll
            for (int i = 0; i < 4; i++) { v[i] = tile[l][lane + 32*i]; sum += v[i]; }
            #pragma unroll
            for (int o = 16; o; o >>= 1) sum += __shfl_xor_sync(0xffffffffu, sum, o);
            float mu = sum * (1.0f/Hd);
            float var = 0.f;
            #pragma unroll
            for (int i = 0; i < 4; i++) { float t = v[i]-mu; var += t*t; }
            #pragma unroll
            for (int o = 16; o; o >>= 1) var += __shfl_xor_sync(0xffffffffu, var, o);
            float rstd = rsqrtf(var * (1.0f/Hd) + 1e-5f);
            #pragma unroll
            for (int i = 0; i < 4; i++) {
                int cc = lane + 32*i;
                tile[l][cc] = (v[i]-mu)*rstd*nw[cc] + nb[cc];
            }
        }
        __syncthreads();
        for (int idx = tid; idx < 64*Hd; idx += 512) {
            int hh = idx >> 6, l = idx & 63;
            g_hnT[((size_t)(b*Hd + hh))*Lseq + l0 + l] = tile[l][hh];
        }
    } else {
        int o = tid & 63, rg = tid >> 6;
        ull acc[4];
        {
            float bv = dec_bias[o];
            ull bp = pk(bv, bv);
            #pragma unroll
            for (int p = 0; p < 4; p++) acc[p] = bp;
        }
        #pragma unroll 2
        for (int k = 0; k < Hd; k++) {
            float wv = __ldg(&g_decWT[k*OUTF + o]);
            ull wp = pk(wv, wv);
            #pragma unroll
            for (int p = 0; p < 4; p++) {
                int r = rg*8 + 2*p;
                acc[p] = ffma2(pk(tile[r][k], tile[r+1][k]), wp, acc[p]);
            }
        }
        #pragma unroll
        for (int p = 0; p < 4; p++) {
            float y0, y1;
            upk(acc[p], y0, y1);
            int r = rg*8 + 2*p;
            out[(size_t)(row0 + r)*OUTF + o]     = y0;
            out[(size_t)(row0 + r + 1)*OUTF + o] = y1;
        }
    }
}

// ---------------- launch ----------------
extern "C" void kernel_launch(void* const* d_in, const int* in_sizes, int n_in,
                              void* d_out, int out_size) {
    const float* x       = (const float*)d_in[0];
    const float* enc_w   = (const float*)d_in[2];
    const float* enc_b   = (const float*)d_in[3];
    const float* dec_w   = (const float*)d_in[4];
    const float* dec_b   = (const float*)d_in[5];
    const float* lam_re  = (const float*)d_in[6];
    const float* lam_im  = (const float*)d_in[7];
    const float* p_re    = (const float*)d_in[8];
    const float* p_im    = (const float*)d_in[9];
    const float* b_re    = (const float*)d_in[10];
    const float* b_im    = (const float*)d_in[11];
    const float* c_re    = (const float*)d_in[12];
    const float* c_im    = (const float*)d_in[13];
    const float* dvec    = (const float*)d_in[14];
    const float* logstep = (const float*)d_in[15];
    const float* norm_w  = (const float*)d_in[16];
    const float* norm_b  = (const float*)d_in[17];
    const float* w1      = (const float*)d_in[18];
    const float* b1      = (const float*)d_in[19];
    const float* w2      = (const float*)d_in[20];
    const float* b2      = (const float*)d_in[21];
    float* out = (float*)d_out;

    int smem_front = 8192 + 8704 + 32*129*4 + 128;   // 33.5 KB
    cudaFuncSetAttribute(front_kernel, cudaFuncAttributeMaxDynamicSharedMemorySize, smem_front);
    cudaFuncSetAttribute(mlp_kernel, cudaFuncAttributeMaxDynamicSharedMemorySize, MLP_SMEM);

    prep_kernel<<<(NLAY*Hd*Hd + 255)/256, 256>>>(enc_w, dec_w, w1, w2);
    front_kernel<<<1024, 512, smem_front>>>(x, enc_b, norm_w, norm_b,
                                            lam_re, lam_im, p_re, p_im,
                                            b_re, b_im, c_re, c_im, logstep);
    for (int i = 0; i < NLAY; i++) {
        conv_kernel<<<Bsz*Hd/2, 256>>>(dvec + i*Hd, i);
        int last = (i == NLAY-1);
        mlp_kernel<<<ROWS/64, 512, MLP_SMEM>>>(b1 + i*Hd, b2 + i*Hd,
                                               norm_w + (last ? 0 : (i+1)*Hd),
                                               norm_b + (last ? 0 : (i+1)*Hd),
                                               dec_b, out,
                                               i, last ? 0 : 1);
    }
}